// round 1
// baseline (speedup 1.0000x reference)
#include <cuda_runtime.h>
#include <cstdint>
#include <cstddef>
#include <vector>
#include <algorithm>
#include <numeric>
#include <cmath>

// FFTLowFreqSelector: out[b,k] = mean_c log1p(|FFT2(x[b,c])|_shifted[idx_k] + 1e-12)
// Only 25 low-frequency bins are needed: signed freqs in {-3..2}^2.
// Direct 4-harmonic separable DFT (m=0..3 cos/sin moments), quadrant-factored.

#define KOUT 25
#define NW   4
#define NT   128

struct Combo {
    int   mx[KOUT];
    int   my[KOUT];
    float sgx[KOUT];
    float sgy[KOUT];
};

// acc layout: CC 16 | CS 12 (my=1..3) | SC 12 (mx=1..3) | SS 9
#define ACC_CC(a,b) acc[(a)*4+(b)]
#define ACC_CS(a,b) acc[16+(a)*3+((b)-1)]
#define ACC_SC(a,b) acc[28+((a)-1)*4+(b)]
#define ACC_SS(a,b) acc[40+((a)-1)*3+((b)-1)]

__global__ __launch_bounds__(NT, 3)
void fft_lowfreq_kernel(const float* __restrict__ x, float* __restrict__ out,
                        int nchan, Combo cb)
{
    const int b    = blockIdx.x;
    const int tid  = threadIdx.x;
    const int lane = tid & 31;
    const int warp = tid >> 5;

    __shared__ float ytw[32][6];   // per y0: cy1,sy1,cy2,sy2,cy3,sy3
    __shared__ float red[NW][49];
    __shared__ float F[4][4][4];   // [type CC/CS/SC/SS][mx][my]

    // y-twiddle table (y0 in [0,32), m=1..3) via quadrant decomposition later
    if (tid < 96) {
        int y0 = tid & 31;
        int m  = (tid >> 5) + 1;
        float s, c;
        sincospif((float)(m * y0) * (1.0f / 64.0f), &s, &c); // angle = 2*pi*m*y0/128
        ytw[y0][(m - 1) * 2 + 0] = c;
        ytw[y0][(m - 1) * 2 + 1] = s;
    }

    // per-lane x twiddles: angle = 2*pi*m*lane/128 = pi*(m*lane/64)
    float cx1, sx1, cx2, sx2, cx3, sx3;
    sincospif((float)lane       * (1.0f / 64.0f), &sx1, &cx1);
    sincospif((float)(2 * lane) * (1.0f / 64.0f), &sx2, &cx2);
    sincospif((float)(3 * lane) * (1.0f / 64.0f), &sx3, &cx3);

    __syncthreads();

    const float* base = x + (size_t)b * nchan * 128 * 128;
    float chanSum = 0.0f;

    for (int c = 0; c < nchan; ++c) {
        const float* img = base + (size_t)c * 128 * 128 + lane;

        float acc[49];
        #pragma unroll
        for (int i = 0; i < 49; ++i) acc[i] = 0.0f;

        #pragma unroll 2
        for (int q = 0; q < 32 / NW; ++q) {
            const int y0 = warp + q * NW;

            // load 4 rows (y0+32r) x 4 cols (lane+32j): coalesced 128B per (r,j)
            float v[4][4];
            #pragma unroll
            for (int r = 0; r < 4; ++r) {
                #pragma unroll
                for (int j = 0; j < 4; ++j)
                    v[r][j] = img[(y0 + 32 * r) * 128 + 32 * j];
            }

            // stage 1: per-row cos/sin moments over this lane's x-subset
            float RC[4][4], RS[4][4];
            #pragma unroll
            for (int r = 0; r < 4; ++r) {
                float a0 = v[r][0], a1 = v[r][1], a2 = v[r][2], a3 = v[r][3];
                float u  = a0 - a2, t  = a1 - a3;
                float w2 = a0 + a2, z2 = a1 + a3;
                float d  = w2 - z2;
                RC[r][0] = w2 + z2;
                RC[r][1] = u * cx1 - t * sx1;   RS[r][1] = u * sx1 + t * cx1;
                RC[r][2] = d * cx2;             RS[r][2] = d * sx2;
                RC[r][3] = u * cx3 + t * sx3;   RS[r][3] = u * sx3 - t * cx3;
                RS[r][0] = 0.0f;
            }

            const float cy1 = ytw[y0][0], sy1 = ytw[y0][1];
            const float cy2 = ytw[y0][2], sy2 = ytw[y0][3];
            const float cy3 = ytw[y0][4], sy3 = ytw[y0][5];

            // stage 2: y quadrant combine into 49 moment accumulators
            #pragma unroll
            for (int m = 0; m < 4; ++m) {
                {
                    float uq = RC[0][m] - RC[2][m];
                    float wq = RC[0][m] + RC[2][m];
                    float vq = RC[1][m] - RC[3][m];
                    float zq = RC[1][m] + RC[3][m];
                    float dq = wq - zq;
                    ACC_CC(m,0) += wq + zq;
                    ACC_CC(m,1) += uq * cy1 - vq * sy1;
                    ACC_CS(m,1) += uq * sy1 + vq * cy1;
                    ACC_CC(m,2) += dq * cy2;
                    ACC_CS(m,2) += dq * sy2;
                    ACC_CC(m,3) += uq * cy3 + vq * sy3;
                    ACC_CS(m,3) += uq * sy3 - vq * cy3;
                }
                if (m >= 1) {
                    float uq = RS[0][m] - RS[2][m];
                    float wq = RS[0][m] + RS[2][m];
                    float vq = RS[1][m] - RS[3][m];
                    float zq = RS[1][m] + RS[3][m];
                    float dq = wq - zq;
                    ACC_SC(m,0) += wq + zq;
                    ACC_SC(m,1) += uq * cy1 - vq * sy1;
                    ACC_SS(m,1) += uq * sy1 + vq * cy1;
                    ACC_SC(m,2) += dq * cy2;
                    ACC_SS(m,2) += dq * sy2;
                    ACC_SC(m,3) += uq * cy3 + vq * sy3;
                    ACC_SS(m,3) += uq * sy3 - vq * cy3;
                }
            }
        }

        // intra-warp butterfly reduce all 49 sums
        #pragma unroll
        for (int i = 0; i < 49; ++i) {
            #pragma unroll
            for (int off = 16; off > 0; off >>= 1)
                acc[i] += __shfl_xor_sync(0xffffffffu, acc[i], off);
        }

        __syncthreads();   // previous channel's F readers are done
        if (lane == 0) {
            #pragma unroll
            for (int i = 0; i < 49; ++i) red[warp][i] = acc[i];
        }
        if (tid < 64) (&F[0][0][0])[tid] = 0.0f;
        __syncthreads();

        if (tid < 49) {
            float s = red[0][tid] + red[1][tid] + red[2][tid] + red[3][tid];
            int type, mx, my;
            if (tid < 16)      { type = 0; mx = tid >> 2;        my = tid & 3;     }
            else if (tid < 28) { int j = tid - 16; type = 1; mx = j / 3;     my = j % 3 + 1; }
            else if (tid < 40) { int j = tid - 28; type = 2; mx = j / 4 + 1; my = j % 4;     }
            else               { int j = tid - 40; type = 3; mx = j / 3 + 1; my = j % 3 + 1; }
            F[type][mx][my] = s;
        }
        __syncthreads();

        // X[fy,fx] = (CC - sx*sy*SS) - i*(sx*SC + sy*CS), fx = sx*mx, fy = sy*my
        if (tid < KOUT) {
            int   mx = cb.mx[tid], my = cb.my[tid];
            float sx = cb.sgx[tid], sy = cb.sgy[tid];
            float re = F[0][mx][my] - sx * sy * F[3][mx][my];
            float im = -(sx * F[2][mx][my] + sy * F[1][mx][my]);
            float mag = sqrtf(re * re + im * im);
            chanSum += log1pf(mag + 1e-12f);
        }
    }

    if (tid < KOUT)
        out[(size_t)b * KOUT + tid] = chanSum * (1.0f / (float)nchan);
}

// Host: replicate numpy's _lowfreq_indices exactly (stable argsort by angle,
// then stable argsort by r^2; r^2 is exact in fp32 so tie classes match).
static void build_combo(Combo& cb)
{
    const int Hh = 128, Ww = 128, HW = Hh * Ww;
    std::vector<float> r2(HW), ang(HW);
    for (int y = 0; y < Hh; ++y) {
        for (int xx = 0; xx < Ww; ++xx) {
            float dy = (float)y  - 63.5f;
            float dx = (float)xx - 63.5f;
            r2[y * Ww + xx]  = dy * dy + dx * dx;
            ang[y * Ww + xx] = atan2f(dy, dx);
        }
    }
    std::vector<int> idx(HW);
    std::iota(idx.begin(), idx.end(), 0);
    std::stable_sort(idx.begin(), idx.end(),
                     [&](int a, int b) { return ang[a] < ang[b]; });
    std::stable_sort(idx.begin(), idx.end(),
                     [&](int a, int b) { return r2[a] < r2[b]; });

    for (int k = 0; k < KOUT; ++k) {
        int s  = idx[k];
        int sy = s / Ww, sx = s % Ww;
        int fy = sy - Hh / 2;       // fftshift inverse for even H
        int fx = sx - Ww / 2;
        cb.my[k]  = fy < 0 ? -fy : fy;
        cb.mx[k]  = fx < 0 ? -fx : fx;
        cb.sgy[k] = fy < 0 ? -1.0f : 1.0f;
        cb.sgx[k] = fx < 0 ? -1.0f : 1.0f;
    }
}

extern "C" void kernel_launch(void* const* d_in, const int* in_sizes, int n_in,
                              void* d_out, int out_size)
{
    const float* x   = (const float*)d_in[0];
    float*       out = (float*)d_out;

    const int CH = 3, HH = 128, WW = 128;
    const int B = in_sizes[0] / (CH * HH * WW);

    Combo cb;
    build_combo(cb);

    fft_lowfreq_kernel<<<B, NT>>>(x, out, CH, cb);
}

// round 4
// speedup vs baseline: 1.1746x; 1.1746x over previous
#include <cuda_runtime.h>
#include <cstdint>
#include <cstddef>
#include <vector>
#include <algorithm>
#include <numeric>
#include <cmath>

// FFTLowFreqSelector: out[b,k] = mean_c log1p(|FFT2(x[b,c])|_shifted[idx_k] + 1e-12)
// Only 25 low-frequency bins needed: signed freqs in {-3..2}^2 -> 4-harmonic
// separable DFT. Two-pass: K1 computes per-column y-moments (7 per column) into
// a device scratch; K2 does the x-transform + combine. Removes the 49-accum
// register pressure and most of the warp-reduction cost of the fused version.

#define KOUT 25
#define MAXB 2048

// scratch: [img][m 0..6][x 0..127], m order: C0,C1,S1,C2,S2,C3,S3
__device__ float g_ymom[(size_t)MAXB * 3 * 7 * 128];

struct Combo {
    int   iCC[KOUT], iCS[KOUT], iSC[KOUT], iSS[KOUT];
    float sgx[KOUT], sgy[KOUT];
};

// ---------------- Kernel 1: y-direction DFT moments per column ----------------
// warp w of block handles image img = blockIdx.x*4 + w.
// lane owns columns 4*lane .. 4*lane+3 (float4 loads).
__global__ __launch_bounds__(128, 6)
void k1_ymom(const float* __restrict__ x, float* __restrict__ ym, int nimg)
{
    __shared__ float ytw[32][6];   // per y0: c1,s1,c2,s2,c3,s3
    const int tid  = threadIdx.x;
    const int lane = tid & 31;
    const int warp = tid >> 5;

    if (tid < 32) {
        float s1, c1, s2, c2, s3, c3;
        sincospif((float)tid * (1.0f / 64.0f), &s1, &c1);
        sincospif((float)tid * (2.0f / 64.0f), &s2, &c2);
        sincospif((float)tid * (3.0f / 64.0f), &s3, &c3);
        ytw[tid][0] = c1; ytw[tid][1] = s1;
        ytw[tid][2] = c2; ytw[tid][3] = s2;
        ytw[tid][4] = c3; ytw[tid][5] = s3;
    }
    __syncthreads();

    const int img = blockIdx.x * 4 + warp;
    if (img >= nimg) return;

    const float4* p = (const float4*)(x + (size_t)img * 16384) + lane;

    float Ax[7], Ay[7], Az[7], Aw[7];
    #pragma unroll
    for (int m = 0; m < 7; ++m) { Ax[m] = Ay[m] = Az[m] = Aw[m] = 0.0f; }

    // y-quadrant: rows y0, y0+32, y0+64, y0+96; phase shift i^m per +32.
    #define COLP(a0, a1, a2, a3, A)                                  \
    {                                                                \
        float u = (a0) - (a2), w = (a0) + (a2);                      \
        float v = (a1) - (a3), z = (a1) + (a3);                      \
        float d = w - z;                                             \
        A[0] += w + z;                                               \
        A[1] += u * c1 - v * s1;                                     \
        A[2] += u * s1 + v * c1;                                     \
        A[3] += d * c2;                                              \
        A[4] += d * s2;                                              \
        A[5] += u * c3 + v * s3;                                     \
        A[6] += u * s3 - v * c3;                                     \
    }

    #pragma unroll 2
    for (int q = 0; q < 32; ++q) {
        float4 a0 = p[q * 32];
        float4 a1 = p[(q + 32) * 32];
        float4 a2 = p[(q + 64) * 32];
        float4 a3 = p[(q + 96) * 32];

        const float c1 = ytw[q][0], s1 = ytw[q][1];
        const float c2 = ytw[q][2], s2 = ytw[q][3];
        const float c3 = ytw[q][4], s3 = ytw[q][5];

        COLP(a0.x, a1.x, a2.x, a3.x, Ax)
        COLP(a0.y, a1.y, a2.y, a3.y, Ay)
        COLP(a0.z, a1.z, a2.z, a3.z, Az)
        COLP(a0.w, a1.w, a2.w, a3.w, Aw)
    }
    #undef COLP

    float4* o = (float4*)(ym + (size_t)img * 7 * 128) + lane;
    #pragma unroll
    for (int m = 0; m < 7; ++m)
        o[m * 32] = make_float4(Ax[m], Ay[m], Az[m], Aw[m]);
}

// ---------------- Kernel 2: x-direction DFT + combine ----------------
// block per batch b (96 threads); warp c handles channel c.
// 49-sum layout: CC 16 (mx*4+my) | CS 12 (16+mx*3+my-1) | SC 12 (28+(mx-1)*4+my)
//              | SS 9 (40+(mx-1)*3+my-1); slots 49..63 stay zero.
__global__ __launch_bounds__(96)
void k2_xmom(const float* __restrict__ ym, float* __restrict__ out, Combo cb)
{
    __shared__ float red[3][64];
    const int b    = blockIdx.x;
    const int tid  = threadIdx.x;
    const int lane = tid & 31;
    const int c    = tid >> 5;

    for (int i = tid; i < 3 * 64; i += 96) (&red[0][0])[i] = 0.0f;

    float c1, s1, c2, s2, c3, s3;
    sincospif((float)lane * (1.0f / 64.0f), &s1, &c1);
    sincospif((float)lane * (2.0f / 64.0f), &s2, &c2);
    sincospif((float)lane * (3.0f / 64.0f), &s3, &c3);

    float acc[49];
    const float* g = ym + (size_t)(b * 3 + c) * 7 * 128;

    // row r -> (my, sin?): my = (r+1)/2 ; sin for r = 2,4,6
    #pragma unroll
    for (int r = 0; r < 7; ++r) {
        const float* row = g + r * 128;
        float a0 = row[lane], a1 = row[lane + 32];
        float a2 = row[lane + 64], a3 = row[lane + 96];
        float u = a0 - a2, w = a0 + a2;
        float v = a1 - a3, z = a1 + a3;
        float d = w - z;

        const int  my = (r + 1) >> 1;
        const bool sn = (r == 2) | (r == 4) | (r == 6);
        #define TGTC(mx) (sn ? (16 + (mx) * 3 + my - 1) : ((mx) * 4 + my))
        #define TGTS(mx) (sn ? (40 + ((mx) - 1) * 3 + my - 1) : (28 + ((mx) - 1) * 4 + my))
        acc[TGTC(0)] = w + z;
        acc[TGTC(1)] = u * c1 - v * s1;
        acc[TGTS(1)] = u * s1 + v * c1;
        acc[TGTC(2)] = d * c2;
        acc[TGTS(2)] = d * s2;
        acc[TGTC(3)] = u * c3 + v * s3;
        acc[TGTS(3)] = u * s3 - v * c3;
        #undef TGTC
        #undef TGTS
    }

    // butterfly reduce 49 sums across the warp
    #pragma unroll
    for (int i = 0; i < 49; ++i) {
        #pragma unroll
        for (int off = 16; off > 0; off >>= 1)
            acc[i] += __shfl_xor_sync(0xffffffffu, acc[i], off);
    }

    if (lane == 0) {
        #pragma unroll
        for (int i = 0; i < 49; ++i) red[c][i] = acc[i];
    }
    __syncthreads();

    // X[fy,fx] = (CC - sx*sy*SS) - i*(sx*SC + sy*CS)
    if (tid < KOUT) {
        const float sx = cb.sgx[tid], sy = cb.sgy[tid];
        float sum = 0.0f;
        #pragma unroll
        for (int cc = 0; cc < 3; ++cc) {
            const float* F = red[cc];
            float re = F[cb.iCC[tid]] - sx * sy * F[cb.iSS[tid]];
            float im = -(sx * F[cb.iSC[tid]] + sy * F[cb.iCS[tid]]);
            sum += log1pf(sqrtf(re * re + im * im) + 1e-12f);
        }
        out[(size_t)b * KOUT + tid] = sum * (1.0f / 3.0f);
    }
}

// Host: replicate numpy's _lowfreq_indices exactly (stable argsort by angle,
// then stable argsort by r^2; r^2 exact in fp32 so tie classes match).
static void build_combo(Combo& cb)
{
    const int Hh = 128, Ww = 128, HW = Hh * Ww;
    std::vector<float> r2(HW), ang(HW);
    for (int y = 0; y < Hh; ++y) {
        for (int xx = 0; xx < Ww; ++xx) {
            float dy = (float)y  - 63.5f;
            float dx = (float)xx - 63.5f;
            r2[y * Ww + xx]  = dy * dy + dx * dx;
            ang[y * Ww + xx] = atan2f(dy, dx);
        }
    }
    std::vector<int> idx(HW);
    std::iota(idx.begin(), idx.end(), 0);
    std::stable_sort(idx.begin(), idx.end(),
                     [&](int a, int b) { return ang[a] < ang[b]; });
    std::stable_sort(idx.begin(), idx.end(),
                     [&](int a, int b) { return r2[a] < r2[b]; });

    for (int k = 0; k < KOUT; ++k) {
        int s  = idx[k];
        int sy = s / Ww, sx = s % Ww;
        int fy = sy - Hh / 2;
        int fx = sx - Ww / 2;
        int my = fy < 0 ? -fy : fy;
        int mx = fx < 0 ? -fx : fx;
        cb.sgy[k] = fy < 0 ? -1.0f : 1.0f;
        cb.sgx[k] = fx < 0 ? -1.0f : 1.0f;
        cb.iCC[k] = mx * 4 + my;
        cb.iCS[k] = (my >= 1)              ? (16 + mx * 3 + my - 1)        : 49;
        cb.iSC[k] = (mx >= 1)              ? (28 + (mx - 1) * 4 + my)      : 49;
        cb.iSS[k] = (mx >= 1 && my >= 1)   ? (40 + (mx - 1) * 3 + my - 1)  : 49;
    }
}

extern "C" void kernel_launch(void* const* d_in, const int* in_sizes, int n_in,
                              void* d_out, int out_size)
{
    const float* x   = (const float*)d_in[0];
    float*       out = (float*)d_out;

    const int CH = 3, HH = 128, WW = 128;
    const int B    = in_sizes[0] / (CH * HH * WW);
    const int nimg = B * CH;

    Combo cb;
    build_combo(cb);

    float* ym = nullptr;
    cudaGetSymbolAddress((void**)&ym, g_ymom);

    k1_ymom<<<(nimg + 3) / 4, 128>>>(x, ym, nimg);
    k2_xmom<<<B, 96>>>(ym, out, cb);
}